// round 16
// baseline (speedup 1.0000x reference)
#include <cuda_runtime.h>
#include <cuda_bf16.h>
#include <cstdint>

#define M_DIM 16384
#define N_DIM 1000
#define N_PAD 1024
#define K_DIM 2048
#define BM 128
#define BN 128
#define BK 64
#define NKT (K_DIM / BK)   // 32 k-tiles
#define NSTAGE 3
#define STG_STRIDE 32768u  // A 16KB + B 16KB per stage; 3 stages = 96KB
#define EPS_D2 1e-12f
#define NCHUNK 8
#define CHUNK_ROWS (M_DIM / NCHUNK)   // 2048
#define NCONV 64                      // producer CTAs (first in grid order)
#define NTILES ((M_DIM / BM) * (N_PAD / BN))  // 1024
#define NWORK 304                     // persistent CTAs = 2 x 152 SMs

// ---- scratch (allocation-free: __device__ globals) ----
__device__ __align__(256) __nv_bfloat16 g_xb[(size_t)M_DIM * K_DIM];
__device__ __align__(256) __nv_bfloat16 g_wb[(size_t)N_PAD * K_DIM];
__device__ float g_x2[M_DIM];
__device__ float g_w2[N_PAD];
__device__ int g_cnt[NCHUNK];
__device__ int g_flag[NCHUNK];
__device__ int g_tile;

// ---------------- helpers ----------------
__device__ __forceinline__ void cp_async16(uint32_t smem, const void* gmem) {
    asm volatile("cp.async.cg.shared.global [%0], [%1], 16;\n" :: "r"(smem), "l"(gmem));
}
__device__ __forceinline__ void cp_commit() {
    asm volatile("cp.async.commit_group;\n");
}
template <int Nrem>
__device__ __forceinline__ void cp_wait() {
    asm volatile("cp.async.wait_group %0;\n" :: "n"(Nrem));
}
__device__ __forceinline__ void ldsm_x4(uint32_t& r0, uint32_t& r1, uint32_t& r2, uint32_t& r3,
                                        uint32_t addr) {
    asm volatile("ldmatrix.sync.aligned.m8n8.x4.shared.b16 {%0,%1,%2,%3}, [%4];\n"
                 : "=r"(r0), "=r"(r1), "=r"(r2), "=r"(r3) : "r"(addr));
}
__device__ __forceinline__ void mma16816(float* c,
                                         uint32_t a0, uint32_t a1, uint32_t a2, uint32_t a3,
                                         uint32_t b0, uint32_t b1) {
    asm volatile("mma.sync.aligned.m16n8k16.row.col.f32.bf16.bf16.f32 "
                 "{%0,%1,%2,%3}, {%4,%5,%6,%7}, {%8,%9}, {%0,%1,%2,%3};\n"
                 : "+f"(c[0]), "+f"(c[1]), "+f"(c[2]), "+f"(c[3])
                 : "r"(a0), "r"(a1), "r"(a2), "r"(a3), "r"(b0), "r"(b1));
}

// ---------------- flag/counter reset (runs first, same stream) ----------------
__global__ void reset_kernel() {
    if (threadIdx.x < NCHUNK) { g_cnt[threadIdx.x] = 0; g_flag[threadIdx.x] = 0; }
    if (threadIdx.x == 0) g_tile = 0;
}

// ---------------- per-row converters (warp-collective, MLP=16) ----------------
__device__ __forceinline__ void conv_row_x(const float* __restrict__ src, int row, int lane) {
    const float4* sr = reinterpret_cast<const float4*>(src + (size_t)row * K_DIM);
    __nv_bfloat162* dr = reinterpret_cast<__nv_bfloat162*>(g_xb + (size_t)row * K_DIM);
    float s = 0.f;
    #pragma unroll
    for (int i = 0; i < 16; ++i) {
        const int idx = lane + (i << 5);
        float4 v = sr[idx];
        s += v.x * v.x + v.y * v.y + v.z * v.z + v.w * v.w;
        dr[2 * idx]     = __floats2bfloat162_rn(v.x, v.y);
        dr[2 * idx + 1] = __floats2bfloat162_rn(v.z, v.w);
    }
    #pragma unroll
    for (int o = 16; o > 0; o >>= 1) s += __shfl_xor_sync(0xffffffffu, s, o);
    if (lane == 0) g_x2[row] = s;
}
__device__ __forceinline__ void conv_row_w(const float* __restrict__ src, int row, int lane) {
    __nv_bfloat162* dr = reinterpret_cast<__nv_bfloat162*>(g_wb + (size_t)row * K_DIM);
    float s = 0.f;
    if (row < N_DIM) {
        const float4* sr = reinterpret_cast<const float4*>(src + (size_t)row * K_DIM);
        #pragma unroll
        for (int i = 0; i < 16; ++i) {
            const int idx = lane + (i << 5);
            float4 v = sr[idx];
            s += v.x * v.x + v.y * v.y + v.z * v.z + v.w * v.w;
            dr[2 * idx]     = __floats2bfloat162_rn(v.x, v.y);
            dr[2 * idx + 1] = __floats2bfloat162_rn(v.z, v.w);
        }
    } else {
        const __nv_bfloat162 z = __floats2bfloat162_rn(0.f, 0.f);
        #pragma unroll
        for (int i = 0; i < 16; ++i) {
            const int idx = lane + (i << 5);
            dr[2 * idx] = z; dr[2 * idx + 1] = z;
        }
    }
    #pragma unroll
    for (int o = 16; o > 0; o >>= 1) s += __shfl_xor_sync(0xffffffffu, s, o);
    if (lane == 0) g_w2[row] = s;
}

// ---------------- GEMM helpers (R5 config + XOR ldsm addressing) ----------------
// CTA tile 128x128x64, 8 warps (2M x 4N), warp tile 64x32, f32 acc.
// 3-stage cp.async pipeline (wait<1>), single barrier/iter, b-frag dbuf.
// 96KB smem, 2 CTAs/SM. XOR identity: offset(kk)=offset(0)^(kk<<5);
// stage offsets (0/32768/65536) don't touch swizzle bits 4-6.

__device__ __forceinline__ void load_stage(uint32_t sbase, int buf, int bm, int bn,
                                           int kt, int tid) {
    const int k0 = kt * BK;
    const uint32_t sA = sbase + (uint32_t)buf * STG_STRIDE;
    const uint32_t sB = sA + 16384u;
    #pragma unroll
    for (int i = 0; i < 4; ++i) {
        int ch = tid + (i << 8);
        int r = ch >> 3, c = ch & 7;
        cp_async16(sA + (uint32_t)(((r << 3) | (c ^ (r & 7))) << 4),
                   g_xb + (size_t)(bm + r) * K_DIM + k0 + (c << 3));
    }
    #pragma unroll
    for (int i = 0; i < 4; ++i) {
        int ch = tid + (i << 8);
        int r = ch >> 3, c = ch & 7;
        cp_async16(sB + (uint32_t)(((r << 3) | (c ^ (r & 7))) << 4),
                   g_wb + (size_t)(bn + r) * K_DIM + k0 + (c << 3));
    }
    cp_commit();
}

// ---------------- persistent fused kernel ----------------
__global__ void __launch_bounds__(256, 2)
fused_kernel(const float* __restrict__ x, const float* __restrict__ w,
             const float* __restrict__ scales, float* __restrict__ out) {
    const int bid  = blockIdx.x;
    const int tid  = threadIdx.x;
    const int lane = tid & 31;
    const int wid  = tid >> 5;

    __shared__ int s_tile;

    if (bid < NCONV) {
        // ======== producer phase: convert w, then x chunk by chunk ========
        for (int g = bid; g < N_PAD / 8; g += NCONV)
            conv_row_w(w, g * 8 + wid, lane);
        for (int c = 0; c < NCHUNK; ++c) {
            for (int g = bid; g < CHUNK_ROWS / 8; g += NCONV)
                conv_row_x(x, c * CHUNK_ROWS + g * 8 + wid, lane);
            __syncthreads();
            if (tid == 0) {
                __threadfence();   // release converted data + norms
                if (atomicAdd(&g_cnt[c], 1) == NCONV - 1)
                    atomicExch(&g_flag[c], 1);
            }
        }
        // fall through: producers join the GEMM worker pool
    }

    // ======== persistent GEMM worker (R5 mainloop) ========
    extern __shared__ __align__(128) char smem[];
    const uint32_t sbase = (uint32_t)__cvta_generic_to_shared(smem);
    const int wm = wid & 1;   // 0..1 -> 64 rows each
    const int wn = wid >> 1;  // 0..3 -> 32 cols each
    const float sc = __ldg(scales);

    // tile-invariant ldsm base addresses (kk=0 / buf=0)
    uint32_t preA[4], preB[2];
    #pragma unroll
    for (int mt = 0; mt < 4; ++mt) {
        int r = wm * 64 + mt * 16 + (lane & 15);
        int c = lane >> 4;
        preA[mt] = sbase + (uint32_t)(((r << 3) | (c ^ (r & 7))) << 4);
    }
    #pragma unroll
    for (int nb = 0; nb < 2; ++nb) {
        int r = wn * 32 + nb * 16 + (lane & 7) + ((lane & 16) >> 1);
        int c = (lane >> 3) & 1;
        preB[nb] = sbase + 16384u + (uint32_t)(((r << 3) | (c ^ (r & 7))) << 4);
    }

    for (;;) {
        if (tid == 0) s_tile = atomicAdd(&g_tile, 1);
        __syncthreads();   // publishes s_tile; also fences prior tile's smem reads
        const int t = s_tile;
        if (t >= NTILES) break;

        const int bm = (t >> 3) * BM;
        const int bn = (t & 7) * BN;

        // gate on this tile's M-chunk being converted
        if (tid == 0) {
            const int c = t >> 7;   // 128 tiles per 2048-row chunk
            unsigned f;
            do {
                asm volatile("ld.acquire.gpu.global.u32 %0, [%1];"
                             : "=r"(f) : "l"(&g_flag[c]) : "memory");
                if (f == 0) __nanosleep(128);
            } while (f == 0);
        }
        __syncthreads();

        float acc[4][4][4];
        #pragma unroll
        for (int i = 0; i < 4; ++i)
            #pragma unroll
            for (int j = 0; j < 4; ++j)
                #pragma unroll
                for (int k = 0; k < 4; ++k) acc[i][j][k] = 0.f;

        uint32_t a[4][4];      // JIT A fragments
        uint32_t b[2][2][4];   // double-buffered B fragments

        load_stage(sbase, 0, bm, bn, 0, tid);
        load_stage(sbase, 1, bm, bn, 1, tid);

        #pragma unroll 1
        for (int kt = 0; kt < NKT; ++kt) {
            const int buf = kt % NSTAGE;
            cp_wait<1>();
            __syncthreads();   // single barrier per iteration

            // buffer (kt+2)%3 last read in iter kt-1; barrier above protects it
            if (kt + 2 < NKT) load_stage(sbase, (kt + 2) % NSTAGE, bm, bn, kt + 2, tid);
            else              cp_commit();  // keep group count aligned

            const uint32_t bo = (uint32_t)buf * STG_STRIDE;

            // B frags for kk=0
            #pragma unroll
            for (int nb = 0; nb < 2; ++nb)
                ldsm_x4(b[0][nb][0], b[0][nb][1], b[0][nb][2], b[0][nb][3],
                        preB[nb] + bo);

            #pragma unroll
            for (int kk = 0; kk < 4; ++kk) {   // 4 x k16 per BK=64
                const int cur = kk & 1;
                const uint32_t kx = (uint32_t)kk << 5;
                // A fragments for this kk (latency hidden by 16 warps/SM)
                #pragma unroll
                for (int mt = 0; mt < 4; ++mt)
                    ldsm_x4(a[mt][0], a[mt][1], a[mt][2], a[mt][3],
                            (preA[mt] + bo) ^ kx);
                // prefetch next kk's B fragments
                if (kk < 3) {
                    const uint32_t kx2 = (uint32_t)(kk + 1) << 5;
                    #pragma unroll
                    for (int nb = 0; nb < 2; ++nb)
                        ldsm_x4(b[cur ^ 1][nb][0], b[cur ^ 1][nb][1],
                                b[cur ^ 1][nb][2], b[cur ^ 1][nb][3],
                                (preB[nb] + bo) ^ kx2);
                }
                #pragma unroll
                for (int mt = 0; mt < 4; ++mt)
                    #pragma unroll
                    for (int nt = 0; nt < 4; ++nt)
                        mma16816(acc[mt][nt],
                                 a[mt][0], a[mt][1], a[mt][2], a[mt][3],
                                 b[cur][nt >> 1][(nt & 1) * 2],
                                 b[cur][nt >> 1][(nt & 1) * 2 + 1]);
            }
        }

        // Epilogue: out = -s * sqrt(max(x2 + w2 - 2*cross, eps))
        #pragma unroll
        for (int mt = 0; mt < 4; ++mt) {
            const int row = bm + wm * 64 + mt * 16 + (lane >> 2);
            const float x2a = g_x2[row];
            const float x2b = g_x2[row + 8];
            #pragma unroll
            for (int nt = 0; nt < 4; ++nt) {
                const int col = bn + wn * 32 + nt * 8 + ((lane & 3) << 1);
                if (col < N_DIM) {   // col even, N_DIM even -> col+1 also valid
                    const float w2a = g_w2[col];
                    const float w2b = g_w2[col + 1];
                    float2 v;
                    v.x = -sc * sqrtf(fmaxf(x2a + w2a - 2.f * acc[mt][nt][0], EPS_D2));
                    v.y = -sc * sqrtf(fmaxf(x2a + w2b - 2.f * acc[mt][nt][1], EPS_D2));
                    *reinterpret_cast<float2*>(out + (size_t)row * N_DIM + col) = v;
                    v.x = -sc * sqrtf(fmaxf(x2b + w2a - 2.f * acc[mt][nt][2], EPS_D2));
                    v.y = -sc * sqrtf(fmaxf(x2b + w2b - 2.f * acc[mt][nt][3], EPS_D2));
                    *reinterpret_cast<float2*>(out + (size_t)(row + 8) * N_DIM + col) = v;
                }
            }
        }
    }
}

// ---------------- launch ----------------
extern "C" void kernel_launch(void* const* d_in, const int* in_sizes, int n_in,
                              void* d_out, int out_size) {
    const float* x      = (const float*)d_in[0];  // [16384, 2048]
    const float* w      = (const float*)d_in[1];  // [1000, 2048]
    const float* scales = (const float*)d_in[2];  // [1]
    float* out          = (float*)d_out;          // [16384, 1000]

    cudaFuncSetAttribute(fused_kernel,
                         cudaFuncAttributeMaxDynamicSharedMemorySize,
                         NSTAGE * STG_STRIDE);

    reset_kernel<<<1, 32>>>();
    fused_kernel<<<NWORK, 256, NSTAGE * STG_STRIDE>>>(x, w, scales, out);
}

// round 17
// speedup vs baseline: 1.1133x; 1.1133x over previous
#include <cuda_runtime.h>
#include <cuda_fp16.h>
#include <cstdint>

#define M_DIM 16384
#define N_DIM 1000
#define N_PAD 1024
#define K_DIM 2048
#define BM 128
#define BN 128
#define BK 64
#define NKT (K_DIM / BK)   // 32 k-tiles
#define STG_STRIDE 32768u  // A 16KB + B 16KB per stage; 2 stages = 64KB
#define EPS_D2 1e-12f
#define NCHUNK 16
#define CHUNK_ROWS (M_DIM / NCHUNK)   // 1024
#define NCONV 128                     // producer CTAs (first in grid order)
#define NGEMM ((M_DIM / BM) * (N_PAD / BN))  // 1024

// ---- scratch (allocation-free: __device__ globals) ----
__device__ __align__(256) __half g_xh[(size_t)M_DIM * K_DIM];
__device__ __align__(256) __half g_wh[(size_t)N_PAD * K_DIM];
__device__ float g_x2[M_DIM];
__device__ float g_w2[N_PAD];
__device__ int g_cnt[NCHUNK];
__device__ int g_flag[NCHUNK];

// ---------------- helpers ----------------
__device__ __forceinline__ void cp_async16(uint32_t smem, const void* gmem) {
    asm volatile("cp.async.cg.shared.global [%0], [%1], 16;\n" :: "r"(smem), "l"(gmem));
}
__device__ __forceinline__ void cp_commit() {
    asm volatile("cp.async.commit_group;\n");
}
template <int Nrem>
__device__ __forceinline__ void cp_wait() {
    asm volatile("cp.async.wait_group %0;\n" :: "n"(Nrem));
}
__device__ __forceinline__ void ldsm_x4(uint32_t& r0, uint32_t& r1, uint32_t& r2, uint32_t& r3,
                                        uint32_t addr) {
    asm volatile("ldmatrix.sync.aligned.m8n8.x4.shared.b16 {%0,%1,%2,%3}, [%4];\n"
                 : "=r"(r0), "=r"(r1), "=r"(r2), "=r"(r3) : "r"(addr));
}
// fp16 accumulate MMA (rate-identical to f32-acc on sm_103a; R6 measurement)
__device__ __forceinline__ void mma16816_h(uint32_t* c,
                                           uint32_t a0, uint32_t a1, uint32_t a2, uint32_t a3,
                                           uint32_t b0, uint32_t b1) {
    asm volatile("mma.sync.aligned.m16n8k16.row.col.f16.f16.f16.f16 "
                 "{%0,%1}, {%2,%3,%4,%5}, {%6,%7}, {%0,%1};\n"
                 : "+r"(c[0]), "+r"(c[1])
                 : "r"(a0), "r"(a1), "r"(a2), "r"(a3), "r"(b0), "r"(b1));
}

// ---------------- flag reset (runs first, same stream) ----------------
__global__ void reset_kernel() {
    if (threadIdx.x < NCHUNK) { g_cnt[threadIdx.x] = 0; g_flag[threadIdx.x] = 0; }
}

// ---------------- per-row converters (warp-collective, MLP=16) ----------------
__device__ __forceinline__ void conv_row_x(const float* __restrict__ src, int row, int lane) {
    const float4* sr = reinterpret_cast<const float4*>(src + (size_t)row * K_DIM);
    __half2* dr = reinterpret_cast<__half2*>(g_xh + (size_t)row * K_DIM);
    float s = 0.f;
    #pragma unroll
    for (int i = 0; i < 16; ++i) {
        const int idx = lane + (i << 5);
        float4 v = sr[idx];
        s += v.x * v.x + v.y * v.y + v.z * v.z + v.w * v.w;
        dr[2 * idx]     = __floats2half2_rn(v.x, v.y);
        dr[2 * idx + 1] = __floats2half2_rn(v.z, v.w);
    }
    #pragma unroll
    for (int o = 16; o > 0; o >>= 1) s += __shfl_xor_sync(0xffffffffu, s, o);
    if (lane == 0) g_x2[row] = s;
}
__device__ __forceinline__ void conv_row_w(const float* __restrict__ src, int row, int lane) {
    __half2* dr = reinterpret_cast<__half2*>(g_wh + (size_t)row * K_DIM);
    float s = 0.f;
    if (row < N_DIM) {
        const float4* sr = reinterpret_cast<const float4*>(src + (size_t)row * K_DIM);
        #pragma unroll
        for (int i = 0; i < 16; ++i) {
            const int idx = lane + (i << 5);
            float4 v = sr[idx];
            s += v.x * v.x + v.y * v.y + v.z * v.z + v.w * v.w;
            dr[2 * idx]     = __floats2half2_rn(v.x, v.y);
            dr[2 * idx + 1] = __floats2half2_rn(v.z, v.w);
        }
    } else {
        const __half2 z = __floats2half2_rn(0.f, 0.f);
        #pragma unroll
        for (int i = 0; i < 16; ++i) {
            const int idx = lane + (i << 5);
            dr[2 * idx] = z; dr[2 * idx + 1] = z;
        }
    }
    #pragma unroll
    for (int o = 16; o > 0; o >>= 1) s += __shfl_xor_sync(0xffffffffu, s, o);
    if (lane == 0) g_w2[row] = s;
}

// ---------------- GEMM helpers (R14 config — measured best) ----------------
// CTA tile 128x128x64, 8 warps (2M x 4N), warp tile 64x32, fp16 acc.
// 2-stage cp.async pipeline, JIT fragments, 64KB smem, 3 CTAs/SM = 24 warps.
// XOR ldsm addressing: offset(kk) = offset(0) ^ (kk<<5); stage offset +32768
// disjoint from swizzle bits 4-6 (smem base 128B-aligned).

__device__ __forceinline__ void load_stage(uint32_t sbase, int buf, int bm, int bn,
                                           int kt, int tid) {
    const int k0 = kt * BK;
    const uint32_t sA = sbase + (uint32_t)buf * STG_STRIDE;
    const uint32_t sB = sA + 16384u;
    #pragma unroll
    for (int i = 0; i < 4; ++i) {
        int ch = tid + (i << 8);
        int r = ch >> 3, c = ch & 7;
        cp_async16(sA + (uint32_t)(((r << 3) | (c ^ (r & 7))) << 4),
                   g_xh + (size_t)(bm + r) * K_DIM + k0 + (c << 3));
    }
    #pragma unroll
    for (int i = 0; i < 4; ++i) {
        int ch = tid + (i << 8);
        int r = ch >> 3, c = ch & 7;
        cp_async16(sB + (uint32_t)(((r << 3) | (c ^ (r & 7))) << 4),
                   g_wh + (size_t)(bn + r) * K_DIM + k0 + (c << 3));
    }
    cp_commit();
}

// ---------------- fused kernel: 128 producer CTAs + 1024 GEMM CTAs ----------------
__global__ void __launch_bounds__(256, 3)
fused_kernel(const float* __restrict__ x, const float* __restrict__ w,
             const float* __restrict__ scales, float* __restrict__ out) {
    const int bid  = blockIdx.x;
    const int tid  = threadIdx.x;
    const int lane = tid & 31;
    const int wid  = tid >> 5;

    if (bid < NCONV) {
        // ======== producer role: convert w, then x chunk by chunk ========
        for (int g = bid; g < N_PAD / 8; g += NCONV)
            conv_row_w(w, g * 8 + wid, lane);
        for (int c = 0; c < NCHUNK; ++c) {
            for (int g = bid; g < CHUNK_ROWS / 8; g += NCONV)
                conv_row_x(x, c * CHUNK_ROWS + g * 8 + wid, lane);
            __syncthreads();
            if (tid == 0) {
                __threadfence();   // release converted data + norms
                if (atomicAdd(&g_cnt[c], 1) == NCONV - 1)
                    atomicExch(&g_flag[c], 1);
            }
        }
        return;
    }

    // ======== GEMM role ========
    extern __shared__ __align__(128) char smem[];
    const uint32_t sbase = (uint32_t)__cvta_generic_to_shared(smem);

    const int gid = bid - NCONV;
    const int bm  = (gid >> 3) * BM;
    const int bn  = (gid & 7) * BN;
    const int wm  = wid & 1;   // 0..1 -> 64 rows each
    const int wn  = wid >> 1;  // 0..3 -> 32 cols each

    // precomputed kk=0/buf=0 ldsm addresses (1 LOP3 per ldsm thereafter)
    uint32_t preA[4], preB[2];
    #pragma unroll
    for (int mt = 0; mt < 4; ++mt) {
        int r = wm * 64 + mt * 16 + (lane & 15);
        int c = lane >> 4;
        preA[mt] = sbase + (uint32_t)(((r << 3) | (c ^ (r & 7))) << 4);
    }
    #pragma unroll
    for (int nb = 0; nb < 2; ++nb) {
        int r = wn * 32 + nb * 16 + (lane & 7) + ((lane & 16) >> 1);
        int c = (lane >> 3) & 1;
        preB[nb] = sbase + 16384u + (uint32_t)(((r << 3) | (c ^ (r & 7))) << 4);
    }

    // wait for this M-chunk's data (flag[c] implies w + chunks 0..c converted)
    if (tid == 0) {
        const int c = gid >> 6;   // 64 GEMM CTAs per 1024-row chunk
        unsigned f;
        do {
            asm volatile("ld.acquire.gpu.global.u32 %0, [%1];"
                         : "=r"(f) : "l"(&g_flag[c]) : "memory");
            if (f == 0) __nanosleep(128);
        } while (f == 0);
    }
    __syncthreads();

    uint32_t acc[4][4][2];      // fp16 accumulators (32 regs)
    #pragma unroll
    for (int i = 0; i < 4; ++i)
        #pragma unroll
        for (int j = 0; j < 4; ++j) { acc[i][j][0] = 0u; acc[i][j][1] = 0u; }

    uint32_t a[4][4], b[2][4];  // JIT single-buffered fragments

    load_stage(sbase, 0, bm, bn, 0, tid);

    #pragma unroll 1
    for (int kt = 0; kt < NKT; ++kt) {
        const int buf = kt & 1;
        if (kt + 1 < NKT) { load_stage(sbase, buf ^ 1, bm, bn, kt + 1, tid); cp_wait<1>(); }
        else              { cp_wait<0>(); }
        __syncthreads();

        const uint32_t bo = (uint32_t)buf << 15;

        #pragma unroll
        for (int kk = 0; kk < 4; ++kk) {   // 4 x k16 per BK=64
            const uint32_t kx = (uint32_t)kk << 5;
            #pragma unroll
            for (int mt = 0; mt < 4; ++mt)
                ldsm_x4(a[mt][0], a[mt][1], a[mt][2], a[mt][3],
                        (preA[mt] + bo) ^ kx);
            #pragma unroll
            for (int nb = 0; nb < 2; ++nb)
                ldsm_x4(b[nb][0], b[nb][1], b[nb][2], b[nb][3],
                        (preB[nb] + bo) ^ kx);
            #pragma unroll
            for (int mt = 0; mt < 4; ++mt)
                #pragma unroll
                for (int nt = 0; nt < 4; ++nt)
                    mma16816_h(acc[mt][nt],
                               a[mt][0], a[mt][1], a[mt][2], a[mt][3],
                               b[nt >> 1][(nt & 1) * 2],
                               b[nt >> 1][(nt & 1) * 2 + 1]);
        }
        __syncthreads();
    }

    // Epilogue: out = -s * sqrt(max(x2 + w2 - 2*cross, eps))
    const float sc = __ldg(scales);
    #pragma unroll
    for (int mt = 0; mt < 4; ++mt) {
        const int row = bm + wm * 64 + mt * 16 + (lane >> 2);
        const float x2a = g_x2[row];
        const float x2b = g_x2[row + 8];
        #pragma unroll
        for (int nt = 0; nt < 4; ++nt) {
            const int col = bn + wn * 32 + nt * 8 + ((lane & 3) << 1);
            if (col < N_DIM) {   // col even, N_DIM even -> col+1 also valid
                const float w2a = g_w2[col];
                const float w2b = g_w2[col + 1];
                const float2 cA = __half22float2(*reinterpret_cast<const __half2*>(&acc[mt][nt][0]));
                const float2 cB = __half22float2(*reinterpret_cast<const __half2*>(&acc[mt][nt][1]));
                float2 v;
                v.x = -sc * sqrtf(fmaxf(x2a + w2a - 2.f * cA.x, EPS_D2));
                v.y = -sc * sqrtf(fmaxf(x2a + w2b - 2.f * cA.y, EPS_D2));
                *reinterpret_cast<float2*>(out + (size_t)row * N_DIM + col) = v;
                v.x = -sc * sqrtf(fmaxf(x2b + w2a - 2.f * cB.x, EPS_D2));
                v.y = -sc * sqrtf(fmaxf(x2b + w2b - 2.f * cB.y, EPS_D2));
                *reinterpret_cast<float2*>(out + (size_t)(row + 8) * N_DIM + col) = v;
            }
        }
    }
}

// ---------------- launch ----------------
extern "C" void kernel_launch(void* const* d_in, const int* in_sizes, int n_in,
                              void* d_out, int out_size) {
    const float* x      = (const float*)d_in[0];  // [16384, 2048]
    const float* w      = (const float*)d_in[1];  // [1000, 2048]
    const float* scales = (const float*)d_in[2];  // [1]
    float* out          = (float*)d_out;          // [16384, 1000]

    cudaFuncSetAttribute(fused_kernel,
                         cudaFuncAttributeMaxDynamicSharedMemorySize,
                         2 * STG_STRIDE);

    reset_kernel<<<1, 32>>>();
    fused_kernel<<<NCONV + NGEMM, 256, 2 * STG_STRIDE>>>(x, w, scales, out);
}